// round 14
// baseline (speedup 1.0000x reference)
#include <cuda_runtime.h>
#include <cuda_fp16.h>
#include <cstdint>

#define SEQ 2048
#define HD  64
#define BH  64
#define MT  8192

// ---- scratch: fp16 bit patterns ----
__device__ __align__(1024) uint16_t g_x16[MT*1024];
__device__ __align__(1024) uint16_t g_w16[3][1024*1024];
__device__ __align__(1024) uint16_t g_q16[BH*SEQ*HD], g_k16[BH*SEQ*HD];
__device__ __align__(1024) uint16_t g_v16[BH*SEQ*HD];

// ---- helpers ----
__device__ __forceinline__ uint32_t s2u(const void* p){
    uint32_t a;
    asm("{ .reg .u64 t; cvta.to.shared.u64 t, %1; cvt.u32.u64 %0, t; }" : "=r"(a) : "l"(p));
    return a;
}
__device__ __forceinline__ void cpa(uint32_t dst, const void* src){
    asm volatile("cp.async.cg.shared.global [%0], [%1], 16;" :: "r"(dst), "l"(src));
}
#define CPC()  asm volatile("cp.async.commit_group;" ::: "memory")
#define CPW(n) asm volatile("cp.async.wait_group %0;" :: "n"(n) : "memory")

__device__ __forceinline__ void ldsm4(uint32_t* r, uint32_t a){
    asm volatile("ldmatrix.sync.aligned.m8n8.x4.shared.b16 {%0,%1,%2,%3}, [%4];"
        : "=r"(r[0]),"=r"(r[1]),"=r"(r[2]),"=r"(r[3]) : "r"(a));
}
__device__ __forceinline__ void ldsm4t(uint32_t* r, uint32_t a){
    asm volatile("ldmatrix.sync.aligned.m8n8.x4.trans.shared.b16 {%0,%1,%2,%3}, [%4];"
        : "=r"(r[0]),"=r"(r[1]),"=r"(r[2]),"=r"(r[3]) : "r"(a));
}
__device__ __forceinline__ void mmah(float* d, const uint32_t* a, const uint32_t* b){
    asm volatile("mma.sync.aligned.m16n8k16.row.col.f32.f16.f16.f32 "
        "{%0,%1,%2,%3}, {%4,%5,%6,%7}, {%8,%9}, {%0,%1,%2,%3};"
        : "+f"(d[0]), "+f"(d[1]), "+f"(d[2]), "+f"(d[3])
        : "r"(a[0]), "r"(a[1]), "r"(a[2]), "r"(a[3]), "r"(b[0]), "r"(b[1]));
}
__device__ __forceinline__ uint32_t pk2(float a, float b){
    uint32_t h;
    asm("cvt.rn.f16x2.f32 %0, %1, %2;" : "=r"(h) : "f"(b), "f"(a));
    return h;
}
// packed 2^x on the MUFU pipe
__device__ __forceinline__ uint32_t e2x2(uint32_t x){
    uint32_t y;
    asm("ex2.approx.f16x2 %0, %1;" : "=r"(y) : "r"(x));
    return y;
}

// ================= fused convert (x + W in one launch) =================
__global__ void cvt_all(const float* __restrict__ x,
                        const float* __restrict__ Wq, const float* __restrict__ Wk,
                        const float* __restrict__ Wv){
    int bx = blockIdx.x;
    if (bx < 8192){
        int i = (bx * 256 + threadIdx.x) * 4;
        float4 v = *(const float4*)(x + i);
        *(uint2*)(g_x16 + i) = make_uint2(pk2(v.x, v.y), pk2(v.z, v.w));
    } else {
        int z = (bx - 8192) >> 10;
        int i = (((bx - 8192) & 1023) * 256 + threadIdx.x) * 4;
        const float* W = (z==0) ? Wq : (z==1) ? Wk : Wv;
        float4 v = *(const float4*)(W + i);
        *(uint2*)(g_w16[z] + i) = make_uint2(pk2(v.x, v.y), pk2(v.z, v.w));
    }
}

// ================= projection GEMM (fp16 HMMA, BK=64, 3-stage) =============
// BM=128 BN=128 BK=64, 8 warps (2x4), 2 CTAs/SM, one sync per 64-K step.
// SMEM per buf (35840B): X@0 [128][144B], W@18432 [64][272B]. x3 bufs.
#define PJ_BUF 35840u
#define PJ_SMEM (3*35840)
__global__ __launch_bounds__(256, 2)
void proj_tc(const float* __restrict__ bq, const float* __restrict__ bk,
             const float* __restrict__ bv){
    extern __shared__ char sm[];
    const uint32_t smb = s2u(sm);
    const int tid = threadIdx.x, z = blockIdx.z;
    const int n0 = blockIdx.x*128, m0 = blockIdx.y*128;
    const int lane = tid & 31, wid = tid >> 5, wm = wid & 1, wn = wid >> 1;
    const uint16_t* __restrict__ Bw = g_w16[z];

    float acc[4][4][4];
    #pragma unroll
    for (int a=0;a<4;a++) for (int b=0;b<4;b++) for (int c=0;c<4;c++) acc[a][b][c]=0.f;

    const uint32_t loA = (uint32_t)((lane&15)*144 + (lane>>4)*16);
    const uint32_t loB = (uint32_t)((lane&15)*272 + (lane>>4)*16);

    auto issue = [&](int it){
        const int k0 = it*64;
        const uint32_t base = smb + (uint32_t)(it%3)*PJ_BUF;
        #pragma unroll
        for (int i = 0; i < 4; i++){           // X: 128x64 fp16, 144B rows
            int idx = tid + i*256, r = idx>>3, c = idx&7;
            cpa(base + r*144 + c*16, g_x16 + (size_t)(m0+r)*1024 + k0 + c*8);
        }
        #pragma unroll
        for (int i = 0; i < 4; i++){           // W: 64x128 fp16, 272B rows
            int idx = tid + i*256, r = idx>>4, c = idx&15;
            cpa(base + 18432 + r*272 + c*16, Bw + (size_t)(k0+r)*1024 + n0 + c*8);
        }
        CPC();
    };

    issue(0); issue(1);
    for (int it = 0; it < 16; it++){
        const uint32_t base = smb + (uint32_t)(it%3)*PJ_BUF;
        CPW(1);
        __syncthreads();
        if (it < 14) issue(it + 2);
        #pragma unroll
        for (int kf = 0; kf < 4; kf++){
            uint32_t ah[4][4];
            #pragma unroll
            for (int mt = 0; mt < 4; mt++)
                ldsm4(ah[mt], base + loA + (wm*64 + mt*16)*144 + kf*32);
            uint32_t bhf[2][4];
            #pragma unroll
            for (int p = 0; p < 2; p++)
                ldsm4t(bhf[p], base + 18432 + loB + kf*16*272 + wn*64 + p*32);
            #pragma unroll
            for (int mt = 0; mt < 4; mt++)
                #pragma unroll
                for (int nt = 0; nt < 4; nt++){
                    uint32_t b2[2] = { bhf[nt>>1][(nt&1)*2], bhf[nt>>1][(nt&1)*2+1] };
                    mmah(acc[mt][nt], ah[mt], b2);
                }
        }
    }

    // epilogue: bias (+ Q scale), fp16 store [bh][s][d]
    const float* bias = (z==0) ? bq : (z==1) ? bk : bv;
    uint16_t* D = (z==0) ? g_q16 : (z==1) ? g_k16 : g_v16;
    const float CQ = (z==0) ? 0.18033688011112042f : 1.0f;   // log2(e)/8 in Q
    const int g = lane >> 2, q = lane & 3;
    #pragma unroll
    for (int mt = 0; mt < 4; mt++){
        #pragma unroll
        for (int nt = 0; nt < 4; nt++){
            const int col = n0 + wn*32 + nt*8 + q*2;
            const float b0 = __ldg(bias + col), b1 = __ldg(bias + col + 1);
            const int h = col >> 6, d = col & 63;
            #pragma unroll
            for (int hr = 0; hr < 2; hr++){
                const int mrow = m0 + wm*64 + mt*16 + g + hr*8;
                float v0 = (acc[mt][nt][hr*2]   + b0) * CQ;
                float v1 = (acc[mt][nt][hr*2+1] + b1) * CQ;
                const int bb = mrow >> 11, s = mrow & 2047;
                size_t off = ((size_t)(bb*16 + h)*SEQ + s)*HD + d;
                *(uint32_t*)(D + off) = pk2(v0, v1);
            }
        }
    }
}

// ================= attention (fp16 HMMA flash, pipelined halves) ===========
// grid (16, 64), 256 thr, 2 CTAs/SM. Warp w: q rows w*16..+16.
// 128-key smem tiles; per tile: QK0 -> exp0 -> QK1 -> PV0 -> exp1 -> PV1 so
// MUFU exp latency hides under independent MMA streams. 3-stage pipeline.
// SMEM per buf (36864B): K@0 [128][144B], V@18432.
#define AT_BUF 36864u
#define AT_SMEM (3*36864)
__global__ __launch_bounds__(256, 2)
void attn_tc(float* __restrict__ out){
    extern __shared__ char sm[];
    const uint32_t smb = s2u(sm);
    const int tid = threadIdx.x, bh = blockIdx.y, q0 = blockIdx.x*128;
    const int lane = tid & 31, w = tid >> 5;
    const int g = lane >> 2, q = lane & 3;
    const uint32_t lo = (uint32_t)((lane&15)*144 + (lane>>4)*16);

    // stage Q through buf0, extract A-fragments
    #pragma unroll
    for (int i = 0; i < 4; i++){
        int idx = tid + i*256, r = idx>>3, c = idx&7;
        cpa(smb + r*144 + c*16, g_q16 + ((size_t)bh*SEQ + q0 + r)*HD + c*8);
    }
    CPC(); CPW(0);
    __syncthreads();
    uint32_t qf[4][4];
    #pragma unroll
    for (int kf = 0; kf < 4; kf++)
        ldsm4(qf[kf], smb + lo + w*16*144 + kf*32);
    __syncthreads();

    float oacc[8][4];
    #pragma unroll
    for (int i=0;i<8;i++) for (int j=0;j<4;j++) oacc[i][j]=0.f;
    float l0 = 0.f, l1 = 0.f;

    const uint16_t* __restrict__ kk = g_k16 + (size_t)bh*SEQ*HD;
    const uint16_t* __restrict__ vv = g_v16 + (size_t)bh*SEQ*HD;

    auto issue = [&](int kt){
        const uint32_t base = smb + (uint32_t)(kt%3)*AT_BUF;
        const size_t kb = (size_t)kt*128*HD;
        #pragma unroll
        for (int i = 0; i < 4; i++){
            int idx = tid + i*256, r = idx>>3, c = idx&7;
            uint32_t d = base + r*144 + c*16;
            size_t gg = kb + (size_t)r*HD + c*8;
            cpa(d, kk + gg); cpa(d + 18432, vv + gg);
        }
        CPC();
    };

    // QK for one 64-key half -> sacc
    auto qk_half = [&](uint32_t kbase, float (*sacc)[4], const uint32_t (*qfr)[4]){
        #pragma unroll
        for (int i=0;i<8;i++) for (int j=0;j<4;j++) sacc[i][j]=0.f;
        #pragma unroll
        for (int kf = 0; kf < 4; kf++){
            #pragma unroll
            for (int p = 0; p < 4; p++){
                uint32_t r4[4];
                ldsm4(r4, kbase + lo + p*16*144 + kf*32);
                uint32_t b0[2] = {r4[0], r4[2]}, b1[2] = {r4[1], r4[3]};
                mmah(sacc[2*p],   qfr[kf], b0);
                mmah(sacc[2*p+1], qfr[kf], b1);
            }
        }
    };
    // exp of a half: sacc -> pa[16] + l sums
    auto exp_half = [&](float (*sacc)[4], uint32_t* pa, float& la, float& lb){
        __half2 h0 = __float2half2_rn(0.f), h1 = __float2half2_rn(0.f);
        #pragma unroll
        for (int p = 0; p < 4; p++){
            pa[4*p+0] = e2x2(pk2(sacc[2*p][0],   sacc[2*p][1]));
            pa[4*p+1] = e2x2(pk2(sacc[2*p][2],   sacc[2*p][3]));
            pa[4*p+2] = e2x2(pk2(sacc[2*p+1][0], sacc[2*p+1][1]));
            pa[4*p+3] = e2x2(pk2(sacc[2*p+1][2], sacc[2*p+1][3]));
            h0 = __hadd2(h0, *(__half2*)&pa[4*p+0]);
            h0 = __hadd2(h0, *(__half2*)&pa[4*p+2]);
            h1 = __hadd2(h1, *(__half2*)&pa[4*p+1]);
            h1 = __hadd2(h1, *(__half2*)&pa[4*p+3]);
        }
        float2 f0 = __half22float2(h0); la += f0.x + f0.y;
        float2 f1 = __half22float2(h1); lb += f1.x + f1.y;
    };
    // PV of a half with precomputed pa
    auto pv_half = [&](uint32_t vbase, const uint32_t* pa){
        #pragma unroll
        for (int p = 0; p < 4; p++){
            #pragma unroll
            for (int dn = 0; dn < 4; dn++){
                uint32_t v4[4];
                ldsm4t(v4, vbase + lo + p*16*144 + dn*32);
                uint32_t b0[2] = {v4[0], v4[1]}, b1[2] = {v4[2], v4[3]};
                mmah(oacc[2*dn],   &pa[4*p], b0);
                mmah(oacc[2*dn+1], &pa[4*p], b1);
            }
        }
    };

    issue(0); issue(1);
    #pragma unroll 1
    for (int kt = 0; kt < 16; kt++){
        const uint32_t base = smb + (uint32_t)(kt%3)*AT_BUF;
        CPW(1);
        __syncthreads();
        if (kt < 14) issue(kt + 2);

        float sacc[8][4];
        uint32_t pa0[16], pa1[16];
        qk_half(base, sacc, qf);                       // QK half 0
        exp_half(sacc, pa0, l0, l1);                   // exp 0 (hidden by QK1)
        qk_half(base + 64u*144u, sacc, qf);            // QK half 1
        pv_half(base + 18432u, pa0);                   // PV 0 (hides exp1 below)
        exp_half(sacc, pa1, l0, l1);                   // exp 1
        pv_half(base + 18432u + 64u*144u, pa1);        // PV 1
    }

    // finish row sums (quad lanes share a row), normalize, store
    l0 += __shfl_xor_sync(0xFFFFFFFFu, l0, 1); l0 += __shfl_xor_sync(0xFFFFFFFFu, l0, 2);
    l1 += __shfl_xor_sync(0xFFFFFFFFu, l1, 1); l1 += __shfl_xor_sync(0xFFFFFFFFu, l1, 2);
    const float i0 = 1.0f / l0, i1 = 1.0f / l1;
    const int b = bh >> 4, h = bh & 15;
    const size_t row = (size_t)b*SEQ + q0 + w*16 + g;
    #pragma unroll
    for (int nt = 0; nt < 8; nt++){
        const int d = nt*8 + q*2;
        size_t o = row*1024 + h*64 + d;
        *(float2*)(out + o)          = make_float2(oacc[nt][0]*i0, oacc[nt][1]*i0);
        *(float2*)(out + o + 8*1024) = make_float2(oacc[nt][2]*i1, oacc[nt][3]*i1);
    }
}

// ================= launch =================
extern "C" void kernel_launch(void* const* d_in, const int* in_sizes, int n_in,
                              void* d_out, int out_size){
    const float* x  = (const float*)d_in[0];
    const float* Wq = (const float*)d_in[1];
    const float* bq = (const float*)d_in[2];
    const float* Wk = (const float*)d_in[3];
    const float* bk = (const float*)d_in[4];
    const float* Wv = (const float*)d_in[5];
    const float* bv = (const float*)d_in[6];
    float* out = (float*)d_out;

    cudaFuncSetAttribute(proj_tc, cudaFuncAttributeMaxDynamicSharedMemorySize, PJ_SMEM);
    cudaFuncSetAttribute(attn_tc, cudaFuncAttributeMaxDynamicSharedMemorySize, AT_SMEM);

    cvt_all<<<8192 + 3072, 256>>>(x, Wq, Wk, Wv);
    proj_tc<<<dim3(8, 64, 3), 256, PJ_SMEM>>>(bq, bk, bv);
    attn_tc<<<dim3(16, 64), 256, AT_SMEM>>>(out);
}

// round 15
// speedup vs baseline: 1.0363x; 1.0363x over previous
#include <cuda_runtime.h>
#include <cuda_fp16.h>
#include <cstdint>

#define SEQ 2048
#define HD  64
#define BH  64
#define MT  8192

// ---- scratch: fp16 bit patterns ----
__device__ __align__(1024) uint16_t g_x16[MT*1024];
__device__ __align__(1024) uint16_t g_w16[3][1024*1024];
__device__ __align__(1024) uint16_t g_q16[BH*SEQ*HD], g_k16[BH*SEQ*HD];
__device__ __align__(1024) uint16_t g_v16[BH*SEQ*HD];

// ---- helpers ----
__device__ __forceinline__ uint32_t s2u(const void* p){
    uint32_t a;
    asm("{ .reg .u64 t; cvta.to.shared.u64 t, %1; cvt.u32.u64 %0, t; }" : "=r"(a) : "l"(p));
    return a;
}
__device__ __forceinline__ void cpa(uint32_t dst, const void* src){
    asm volatile("cp.async.cg.shared.global [%0], [%1], 16;" :: "r"(dst), "l"(src));
}
#define CPC()  asm volatile("cp.async.commit_group;" ::: "memory")
#define CPW(n) asm volatile("cp.async.wait_group %0;" :: "n"(n) : "memory")

__device__ __forceinline__ void ldsm4(uint32_t* r, uint32_t a){
    asm volatile("ldmatrix.sync.aligned.m8n8.x4.shared.b16 {%0,%1,%2,%3}, [%4];"
        : "=r"(r[0]),"=r"(r[1]),"=r"(r[2]),"=r"(r[3]) : "r"(a));
}
__device__ __forceinline__ void ldsm4t(uint32_t* r, uint32_t a){
    asm volatile("ldmatrix.sync.aligned.m8n8.x4.trans.shared.b16 {%0,%1,%2,%3}, [%4];"
        : "=r"(r[0]),"=r"(r[1]),"=r"(r[2]),"=r"(r[3]) : "r"(a));
}
__device__ __forceinline__ void mmah(float* d, const uint32_t* a, const uint32_t* b){
    asm volatile("mma.sync.aligned.m16n8k16.row.col.f32.f16.f16.f32 "
        "{%0,%1,%2,%3}, {%4,%5,%6,%7}, {%8,%9}, {%0,%1,%2,%3};"
        : "+f"(d[0]), "+f"(d[1]), "+f"(d[2]), "+f"(d[3])
        : "r"(a[0]), "r"(a[1]), "r"(a[2]), "r"(a[3]), "r"(b[0]), "r"(b[1]));
}
__device__ __forceinline__ uint32_t pk2(float a, float b){
    uint32_t h;
    asm("cvt.rn.f16x2.f32 %0, %1, %2;" : "=r"(h) : "f"(b), "f"(a));
    return h;
}
// packed 2^x on the MUFU pipe
__device__ __forceinline__ uint32_t e2x2(uint32_t x){
    uint32_t y;
    asm("ex2.approx.f16x2 %0, %1;" : "=r"(y) : "r"(x));
    return y;
}

// ================= fused convert (x + W in one launch) =================
__global__ void cvt_all(const float* __restrict__ x,
                        const float* __restrict__ Wq, const float* __restrict__ Wk,
                        const float* __restrict__ Wv){
    int bx = blockIdx.x;
    if (bx < 8192){
        int i = (bx * 256 + threadIdx.x) * 4;
        float4 v = *(const float4*)(x + i);
        *(uint2*)(g_x16 + i) = make_uint2(pk2(v.x, v.y), pk2(v.z, v.w));
    } else {
        int z = (bx - 8192) >> 10;
        int i = (((bx - 8192) & 1023) * 256 + threadIdx.x) * 4;
        const float* W = (z==0) ? Wq : (z==1) ? Wk : Wv;
        float4 v = *(const float4*)(W + i);
        *(uint2*)(g_w16[z] + i) = make_uint2(pk2(v.x, v.y), pk2(v.z, v.w));
    }
}

// ================= projection GEMM (fp16 HMMA, BK=64, 3-stage) =============
// BM=128 BN=128 BK=64, 8 warps (2x4), 2 CTAs/SM, one sync per 64-K step.
// SMEM per buf (35840B): X@0 [128][144B], W@18432 [64][272B]. x3 bufs.
// Epilogue stages the 128x128 fp16 output tile in buf0 (272B row stride,
// conflict-free) and writes coalesced 128B segments.
#define PJ_BUF 35840u
#define PJ_SMEM (3*35840)
__global__ __launch_bounds__(256, 2)
void proj_tc(const float* __restrict__ bq, const float* __restrict__ bk,
             const float* __restrict__ bv){
    extern __shared__ char sm[];
    const uint32_t smb = s2u(sm);
    const int tid = threadIdx.x, z = blockIdx.z;
    const int n0 = blockIdx.x*128, m0 = blockIdx.y*128;
    const int lane = tid & 31, wid = tid >> 5, wm = wid & 1, wn = wid >> 1;
    const uint16_t* __restrict__ Bw = g_w16[z];

    float acc[4][4][4];
    #pragma unroll
    for (int a=0;a<4;a++) for (int b=0;b<4;b++) for (int c=0;c<4;c++) acc[a][b][c]=0.f;

    const uint32_t loA = (uint32_t)((lane&15)*144 + (lane>>4)*16);
    const uint32_t loB = (uint32_t)((lane&15)*272 + (lane>>4)*16);

    auto issue = [&](int it){
        const int k0 = it*64;
        const uint32_t base = smb + (uint32_t)(it%3)*PJ_BUF;
        #pragma unroll
        for (int i = 0; i < 4; i++){           // X: 128x64 fp16, 144B rows
            int idx = tid + i*256, r = idx>>3, c = idx&7;
            cpa(base + r*144 + c*16, g_x16 + (size_t)(m0+r)*1024 + k0 + c*8);
        }
        #pragma unroll
        for (int i = 0; i < 4; i++){           // W: 64x128 fp16, 272B rows
            int idx = tid + i*256, r = idx>>4, c = idx&15;
            cpa(base + 18432 + r*272 + c*16, Bw + (size_t)(k0+r)*1024 + n0 + c*8);
        }
        CPC();
    };

    issue(0); issue(1);
    for (int it = 0; it < 16; it++){
        const uint32_t base = smb + (uint32_t)(it%3)*PJ_BUF;
        CPW(1);
        __syncthreads();
        if (it < 14) issue(it + 2);
        #pragma unroll
        for (int kf = 0; kf < 4; kf++){
            uint32_t ah[4][4];
            #pragma unroll
            for (int mt = 0; mt < 4; mt++)
                ldsm4(ah[mt], base + loA + (wm*64 + mt*16)*144 + kf*32);
            uint32_t bhf[2][4];
            #pragma unroll
            for (int p = 0; p < 2; p++)
                ldsm4t(bhf[p], base + 18432 + loB + kf*16*272 + wn*64 + p*32);
            #pragma unroll
            for (int mt = 0; mt < 4; mt++)
                #pragma unroll
                for (int nt = 0; nt < 4; nt++){
                    uint32_t b2[2] = { bhf[nt>>1][(nt&1)*2], bhf[nt>>1][(nt&1)*2+1] };
                    mmah(acc[mt][nt], ah[mt], b2);
                }
        }
    }

    // epilogue: bias (+ Q scale), stage fp16 tile in smem, coalesced store
    const float* bias = (z==0) ? bq : (z==1) ? bk : bv;
    uint16_t* D = (z==0) ? g_q16 : (z==1) ? g_k16 : g_v16;
    const float CQ = (z==0) ? 0.18033688011112042f : 1.0f;   // log2(e)/8 in Q
    const int g = lane >> 2, q = lane & 3;
    __syncthreads();                                 // all warps done with buf0
    #pragma unroll
    for (int mt = 0; mt < 4; mt++){
        #pragma unroll
        for (int nt = 0; nt < 4; nt++){
            const int col = n0 + wn*32 + nt*8 + q*2;
            const float b0 = __ldg(bias + col), b1 = __ldg(bias + col + 1);
            const int lc = wn*32 + nt*8 + q*2;       // local col 0..127
            #pragma unroll
            for (int hr = 0; hr < 2; hr++){
                const int lr = wm*64 + mt*16 + g + hr*8;   // local row 0..127
                float v0 = (acc[mt][nt][hr*2]   + b0) * CQ;
                float v1 = (acc[mt][nt][hr*2+1] + b1) * CQ;
                *(uint32_t*)(sm + lr*272 + lc*2) = pk2(v0, v1);
            }
        }
    }
    __syncthreads();
    // coalesced copy: 128 rows x 128 fp16 -> [bh][s][d]; 8 uint4 per thread
    const int bb = m0 >> 11, s0 = m0 & 2047, h0 = n0 >> 6;
    #pragma unroll
    for (int i = 0; i < 8; i++){
        int j = tid + i*256;                 // 0..2047 uint4 slots
        int row = j >> 4, cq = (j & 15) * 8; // cq: fp16 col 0..120
        int head = cq >> 6, d = cq & 63;
        uint4 v = *(uint4*)(sm + row*272 + cq*2);
        size_t off = ((size_t)(bb*16 + h0 + head)*SEQ + s0 + row)*HD + d;
        *(uint4*)(D + off) = v;
    }
}

// ================= attention (fp16 HMMA flash, 128-key tiles) ==============
// grid (16, 64), 256 thr, 2 CTAs/SM. Warp w: q rows w*16..+16.
// 128-key smem tiles processed as two 64-key passes; 3-stage pipeline,
// one sync per 128 keys. SMEM per buf (36864B): K@0 [128][144B], V@18432.
#define AT_BUF 36864u
#define AT_SMEM (3*36864)
__global__ __launch_bounds__(256, 2)
void attn_tc(float* __restrict__ out){
    extern __shared__ char sm[];
    const uint32_t smb = s2u(sm);
    const int tid = threadIdx.x, bh = blockIdx.y, q0 = blockIdx.x*128;
    const int lane = tid & 31, w = tid >> 5;
    const int g = lane >> 2, q = lane & 3;
    const uint32_t lo = (uint32_t)((lane&15)*144 + (lane>>4)*16);

    // stage Q through buf0, extract A-fragments
    #pragma unroll
    for (int i = 0; i < 4; i++){
        int idx = tid + i*256, r = idx>>3, c = idx&7;
        cpa(smb + r*144 + c*16, g_q16 + ((size_t)bh*SEQ + q0 + r)*HD + c*8);
    }
    CPC(); CPW(0);
    __syncthreads();
    uint32_t qf[4][4];
    #pragma unroll
    for (int kf = 0; kf < 4; kf++)
        ldsm4(qf[kf], smb + lo + w*16*144 + kf*32);
    __syncthreads();

    float oacc[8][4];
    #pragma unroll
    for (int i=0;i<8;i++) for (int j=0;j<4;j++) oacc[i][j]=0.f;
    float l0 = 0.f, l1 = 0.f;

    const uint16_t* __restrict__ kk = g_k16 + (size_t)bh*SEQ*HD;
    const uint16_t* __restrict__ vv = g_v16 + (size_t)bh*SEQ*HD;

    auto issue = [&](int kt){
        const uint32_t base = smb + (uint32_t)(kt%3)*AT_BUF;
        const size_t kb = (size_t)kt*128*HD;
        #pragma unroll
        for (int i = 0; i < 4; i++){
            int idx = tid + i*256, r = idx>>3, c = idx&7;
            uint32_t d = base + r*144 + c*16;
            size_t gg = kb + (size_t)r*HD + c*8;
            cpa(d, kk + gg); cpa(d + 18432, vv + gg);
        }
        CPC();
    };

    issue(0); issue(1);
    #pragma unroll 1
    for (int kt = 0; kt < 16; kt++){
        const uint32_t base = smb + (uint32_t)(kt%3)*AT_BUF;
        CPW(1);
        __syncthreads();
        if (kt < 14) issue(kt + 2);

        #pragma unroll
        for (int hf = 0; hf < 2; hf++){
            const uint32_t kbase = base + (uint32_t)hf*64*144;
            // scores: 16 q-rows x 64 keys (f32 accum)
            float sacc[8][4];
            #pragma unroll
            for (int i=0;i<8;i++) for (int j=0;j<4;j++) sacc[i][j]=0.f;
            #pragma unroll
            for (int kf = 0; kf < 4; kf++){
                #pragma unroll
                for (int p = 0; p < 4; p++){
                    uint32_t r4[4];
                    ldsm4(r4, kbase + lo + p*16*144 + kf*32);
                    uint32_t b0[2] = {r4[0], r4[2]}, b1[2] = {r4[1], r4[3]};
                    mmah(sacc[2*p],   qf[kf], b0);
                    mmah(sacc[2*p+1], qf[kf], b1);
                }
            }

            // softmax (packed MUFU exp) + PV (f32 accum)
            __half2 la0 = __float2half2_rn(0.f), la1 = __float2half2_rn(0.f);
            #pragma unroll
            for (int p = 0; p < 4; p++){
                uint32_t pa[4];
                pa[0] = e2x2(pk2(sacc[2*p][0],   sacc[2*p][1]));
                pa[1] = e2x2(pk2(sacc[2*p][2],   sacc[2*p][3]));
                pa[2] = e2x2(pk2(sacc[2*p+1][0], sacc[2*p+1][1]));
                pa[3] = e2x2(pk2(sacc[2*p+1][2], sacc[2*p+1][3]));
                la0 = __hadd2(la0, *(__half2*)&pa[0]);
                la0 = __hadd2(la0, *(__half2*)&pa[2]);
                la1 = __hadd2(la1, *(__half2*)&pa[1]);
                la1 = __hadd2(la1, *(__half2*)&pa[3]);
                #pragma unroll
                for (int dn = 0; dn < 4; dn++){
                    uint32_t v4[4];
                    ldsm4t(v4, base + 18432 + (uint32_t)hf*64*144 + lo + p*16*144 + dn*32);
                    uint32_t b0[2] = {v4[0], v4[1]}, b1[2] = {v4[2], v4[3]};
                    mmah(oacc[2*dn],   pa, b0);
                    mmah(oacc[2*dn+1], pa, b1);
                }
            }
            float2 f0 = __half22float2(la0); l0 += f0.x + f0.y;
            float2 f1 = __half22float2(la1); l1 += f1.x + f1.y;
        }
    }

    // finish row sums (quad lanes share a row), normalize, store
    l0 += __shfl_xor_sync(0xFFFFFFFFu, l0, 1); l0 += __shfl_xor_sync(0xFFFFFFFFu, l0, 2);
    l1 += __shfl_xor_sync(0xFFFFFFFFu, l1, 1); l1 += __shfl_xor_sync(0xFFFFFFFFu, l1, 2);
    const float i0 = 1.0f / l0, i1 = 1.0f / l1;
    const int b = bh >> 4, h = bh & 15;
    const size_t row = (size_t)b*SEQ + q0 + w*16 + g;
    #pragma unroll
    for (int nt = 0; nt < 8; nt++){
        const int d = nt*8 + q*2;
        size_t o = row*1024 + h*64 + d;
        *(float2*)(out + o)          = make_float2(oacc[nt][0]*i0, oacc[nt][1]*i0);
        *(float2*)(out + o + 8*1024) = make_float2(oacc[nt][2]*i1, oacc[nt][3]*i1);
    }
}

// ================= launch =================
extern "C" void kernel_launch(void* const* d_in, const int* in_sizes, int n_in,
                              void* d_out, int out_size){
    const float* x  = (const float*)d_in[0];
    const float* Wq = (const float*)d_in[1];
    const float* bq = (const float*)d_in[2];
    const float* Wk = (const float*)d_in[3];
    const float* bk = (const float*)d_in[4];
    const float* Wv = (const float*)d_in[5];
    const float* bv = (const float*)d_in[6];
    float* out = (float*)d_out;

    cudaFuncSetAttribute(proj_tc, cudaFuncAttributeMaxDynamicSharedMemorySize, PJ_SMEM);
    cudaFuncSetAttribute(attn_tc, cudaFuncAttributeMaxDynamicSharedMemorySize, AT_SMEM);

    cvt_all<<<8192 + 3072, 256>>>(x, Wq, Wk, Wv);
    proj_tc<<<dim3(8, 64, 3), 256, PJ_SMEM>>>(bq, bk, bv);
    attn_tc<<<dim3(16, 64), 256, AT_SMEM>>>(out);
}